// round 4
// baseline (speedup 1.0000x reference)
#include <cuda_runtime.h>
#include <cuda_bf16.h>
#include <math.h>
#include <stdint.h>

#define BH    32
#define SEQ   2048
#define DIM   1024
#define NH    16
#define HDIM  64
#define MROWS 4096

// ---------------- device scratch ----------------
__device__ __nv_bfloat16 g_xh[MROWS * DIM], g_xl[MROWS * DIM];
__device__ __nv_bfloat16 g_Wqh[DIM * DIM], g_Wql[DIM * DIM];
__device__ __nv_bfloat16 g_Wkh[DIM * DIM], g_Wkl[DIM * DIM];
__device__ __nv_bfloat16 g_Wvh[DIM * DIM], g_Wvl[DIM * DIM];
__device__ __nv_bfloat16 g_Woh[DIM * DIM], g_Wol[DIM * DIM];
__device__ __nv_bfloat16 g_Qh[BH * SEQ * HDIM], g_Ql[BH * SEQ * HDIM];   // [bh][s][hd]
__device__ __nv_bfloat16 g_Kh[BH * SEQ * HDIM], g_Kl[BH * SEQ * HDIM];   // [bh][s][hd]
__device__ __nv_bfloat16 g_Vth[BH * HDIM * SEQ], g_Vtl[BH * HDIM * SEQ]; // [bh][hd][s]
__device__ __nv_bfloat16 g_Ah[(size_t)MROWS * DIM], g_Al[(size_t)MROWS * DIM];

// ---------------- helpers ----------------
__device__ __forceinline__ uint32_t smem_u32(const void* p) {
    uint32_t a;
    asm("{ .reg .u64 t; cvta.to.shared.u64 t, %1; cvt.u32.u64 %0, t; }" : "=r"(a) : "l"(p));
    return a;
}
__device__ __forceinline__ void cp16(uint32_t s, const void* g) {
    asm volatile("cp.async.cg.shared.global [%0], [%1], 16;" :: "r"(s), "l"(g));
}
__device__ __forceinline__ void mma_bf16(float* d, const uint32_t* a, const uint32_t* b) {
    asm volatile(
        "mma.sync.aligned.m16n8k16.row.col.f32.bf16.bf16.f32 "
        "{%0,%1,%2,%3}, {%4,%5,%6,%7}, {%8,%9}, {%0,%1,%2,%3};"
        : "+f"(d[0]), "+f"(d[1]), "+f"(d[2]), "+f"(d[3])
        : "r"(a[0]), "r"(a[1]), "r"(a[2]), "r"(a[3]), "r"(b[0]), "r"(b[1]));
}
__device__ __forceinline__ void split2(float v0, float v1, uint32_t& h, uint32_t& l) {
    __nv_bfloat16 h0 = __float2bfloat16(v0), h1 = __float2bfloat16(v1);
    h = ((uint32_t)__bfloat16_as_ushort(h1) << 16) | __bfloat16_as_ushort(h0);
    __nv_bfloat16 l0 = __float2bfloat16(v0 - __bfloat162float(h0));
    __nv_bfloat16 l1 = __float2bfloat16(v1 - __bfloat162float(h1));
    l = ((uint32_t)__bfloat16_as_ushort(l1) << 16) | __bfloat16_as_ushort(l0);
}

// ---------------- split conversion kernels ----------------
__global__ __launch_bounds__(256) void split_kernel(const float* __restrict__ in,
                                                    __nv_bfloat16* __restrict__ h,
                                                    __nv_bfloat16* __restrict__ l, int n) {
    int i = blockIdx.x * 256 + threadIdx.x;
    if (i < n) {
        float v = in[i];
        __nv_bfloat16 hi = __float2bfloat16(v);
        h[i] = hi;
        l[i] = __float2bfloat16(v - __bfloat162float(hi));
    }
}

__global__ __launch_bounds__(256) void wsplit_kernel(const float* __restrict__ W,
                                                     __nv_bfloat16* __restrict__ th,
                                                     __nv_bfloat16* __restrict__ tl) {
    __shared__ float t[32][33];
    int n0 = blockIdx.x * 32, k0 = blockIdx.y * 32;
    int tx = threadIdx.x & 31, ty = threadIdx.x >> 5;
#pragma unroll
    for (int r = ty; r < 32; r += 8)
        t[r][tx] = W[(size_t)(k0 + r) * DIM + n0 + tx];
    __syncthreads();
#pragma unroll
    for (int r = ty; r < 32; r += 8) {
        float v = t[tx][r];
        __nv_bfloat16 hi = __float2bfloat16(v);
        size_t idx = (size_t)(n0 + r) * DIM + k0 + tx;
        th[idx] = hi;
        tl[idx] = __float2bfloat16(v - __bfloat162float(hi));
    }
}

// ---------------- mma.sync split-bf16 projection GEMM ----------------
// modes: 0 Q/K head-split hi/lo, 1 V transposed hi/lo, 2 fp32 out (+bias)
__global__ __launch_bounds__(256, 1) void gemm_kernel(
    const __nv_bfloat16* __restrict__ Ah, const __nv_bfloat16* __restrict__ Al,
    const __nv_bfloat16* __restrict__ Bh, const __nv_bfloat16* __restrict__ Bl,
    const float* __restrict__ bias, float scale, int mode,
    __nv_bfloat16* __restrict__ outH, __nv_bfloat16* __restrict__ outL,
    float* __restrict__ outF)
{
    extern __shared__ char smem[];
    constexpr int TN = 128, WN = 64, NT = 8;
    constexpr int ROWB = 80;
    constexpr int A_H = 0, A_L = 128 * ROWB, B_H = 2 * 128 * ROWB, B_L = 3 * 128 * ROWB;
    constexpr int STAGE = 4 * 128 * ROWB;

    const int tid = threadIdx.x;
    const int w = tid >> 5, lane = tid & 31;
    const int g = lane >> 2, t = lane & 3;
    const int wm = w & 3, wn = w >> 2;
    const int m0 = blockIdx.y * 128, n0 = blockIdx.x * TN;
    const uint32_t sb = smem_u32(smem);

    float acc[2][NT][4] = {};

    auto stage_load = [&](int buf, int c) {
        const int k0 = c << 5;
        const uint32_t so = sb + buf * STAGE;
#pragma unroll
        for (int i = tid; i < 512; i += 256) {
            int r = i >> 2, cc = i & 3;
            uint32_t off = r * ROWB + cc * 16;
            cp16(so + A_H + off, Ah + (size_t)(m0 + r) * DIM + k0 + cc * 8);
            cp16(so + A_L + off, Al + (size_t)(m0 + r) * DIM + k0 + cc * 8);
            cp16(so + B_H + off, Bh + (size_t)(n0 + r) * DIM + k0 + cc * 8);
            cp16(so + B_L + off, Bl + (size_t)(n0 + r) * DIM + k0 + cc * 8);
        }
        asm volatile("cp.async.commit_group;");
    };

    stage_load(0, 0);
    for (int c = 0; c < 32; c++) {
        const int buf = c & 1;
        if (c + 1 < 32) {
            stage_load(buf ^ 1, c + 1);
            asm volatile("cp.async.wait_group 1;");
        } else {
            asm volatile("cp.async.wait_group 0;");
        }
        __syncthreads();
        const char* s = smem + buf * STAGE;
#pragma unroll
        for (int ks = 0; ks < 2; ks++) {
            const int kb = ks * 32 + t * 4;
            uint32_t ah[2][4], al[2][4], bh[NT][2], bl[NT][2];
#pragma unroll
            for (int mt = 0; mt < 2; mt++) {
                const char* p = s + (wm * 32 + mt * 16 + g) * ROWB + kb;
                ah[mt][0] = *(const uint32_t*)(p + A_H);
                ah[mt][1] = *(const uint32_t*)(p + A_H + 8 * ROWB);
                ah[mt][2] = *(const uint32_t*)(p + A_H + 16);
                ah[mt][3] = *(const uint32_t*)(p + A_H + 8 * ROWB + 16);
                al[mt][0] = *(const uint32_t*)(p + A_L);
                al[mt][1] = *(const uint32_t*)(p + A_L + 8 * ROWB);
                al[mt][2] = *(const uint32_t*)(p + A_L + 16);
                al[mt][3] = *(const uint32_t*)(p + A_L + 8 * ROWB + 16);
            }
#pragma unroll
            for (int nt = 0; nt < NT; nt++) {
                const char* p = s + (wn * WN + nt * 8 + g) * ROWB + kb;
                bh[nt][0] = *(const uint32_t*)(p + B_H);
                bh[nt][1] = *(const uint32_t*)(p + B_H + 16);
                bl[nt][0] = *(const uint32_t*)(p + B_L);
                bl[nt][1] = *(const uint32_t*)(p + B_L + 16);
            }
#pragma unroll
            for (int mt = 0; mt < 2; mt++)
#pragma unroll
                for (int nt = 0; nt < NT; nt++) {
                    mma_bf16(acc[mt][nt], ah[mt], bh[nt]);
                    mma_bf16(acc[mt][nt], ah[mt], bl[nt]);
                    mma_bf16(acc[mt][nt], al[mt], bh[nt]);
                }
        }
        __syncthreads();
    }

#pragma unroll
    for (int mt = 0; mt < 2; mt++)
#pragma unroll
        for (int nt = 0; nt < NT; nt++)
#pragma unroll
            for (int p = 0; p < 2; p++) {
                int row = m0 + wm * 32 + mt * 16 + g + 8 * p;
                int col = n0 + wn * WN + nt * 8 + 2 * t;
                float v0 = acc[mt][nt][2 * p + 0];
                float v1 = acc[mt][nt][2 * p + 1];
                if (mode == 2) {
                    *(float2*)(outF + (size_t)row * DIM + col)
                        = make_float2(v0 + bias[col], v1 + bias[col + 1]);
                } else {
                    int b = row >> 11, sq = row & (SEQ - 1);
                    v0 = (v0 + bias[col]) * scale;
                    v1 = (v1 + bias[col + 1]) * scale;
#pragma unroll
                    for (int e = 0; e < 2; e++) {
                        int cc = col + e;
                        float v = e ? v1 : v0;
                        int h = cc >> 6, hd = cc & (HDIM - 1);
                        __nv_bfloat16 hi = __float2bfloat16(v);
                        __nv_bfloat16 lo = __float2bfloat16(v - __bfloat162float(hi));
                        size_t idx = (mode == 0)
                            ? ((((size_t)b * NH + h) * SEQ + sq) * HDIM + hd)
                            : ((((size_t)b * NH + h) * HDIM + hd) * SEQ + sq);
                        outH[idx] = hi;
                        outL[idx] = lo;
                    }
                }
            }
}

// ---------------- fused flash attention (mma.sync, online softmax) ----------------
// grid (SEQ/128, BH), 8 warps x 16 q-rows. K/V chunks of 64, double-buffered.
__global__ __launch_bounds__(256, 1) void flash_kernel()
{
    extern __shared__ char smem[];
    constexpr int ROWB = 144;              // 64 bf16 + 16B pad
    constexpr int TILE = 64 * ROWB;        // 9216
    constexpr int STAGE = 4 * TILE;        // Kh,Kl,Vh,Vl
    constexpr int NCH = SEQ / 64;          // 32

    const int tid = threadIdx.x;
    const int w = tid >> 5, lane = tid & 31;
    const int g = lane >> 2, t = lane & 3;
    const int bh = blockIdx.y, q0 = blockIdx.x * 128;
    const uint32_t sb = smem_u32(smem);

    const __nv_bfloat16* Qh = g_Qh + (size_t)bh * SEQ * HDIM;
    const __nv_bfloat16* Ql = g_Ql + (size_t)bh * SEQ * HDIM;
    const __nv_bfloat16* Kh = g_Kh + (size_t)bh * SEQ * HDIM;
    const __nv_bfloat16* Kl = g_Kl + (size_t)bh * SEQ * HDIM;
    const __nv_bfloat16* Vh = g_Vth + (size_t)bh * HDIM * SEQ;
    const __nv_bfloat16* Vl = g_Vtl + (size_t)bh * HDIM * SEQ;

    const int r0 = q0 + w * 16 + g;

    // Q fragments (held in registers for all chunks)
    uint32_t qh[4][4], ql[4][4];
#pragma unroll
    for (int j = 0; j < 4; j++) {
        int c0 = j * 16 + t * 2;
        qh[j][0] = *(const uint32_t*)(Qh + (size_t)r0 * HDIM + c0);
        qh[j][1] = *(const uint32_t*)(Qh + (size_t)(r0 + 8) * HDIM + c0);
        qh[j][2] = *(const uint32_t*)(Qh + (size_t)r0 * HDIM + c0 + 8);
        qh[j][3] = *(const uint32_t*)(Qh + (size_t)(r0 + 8) * HDIM + c0 + 8);
        ql[j][0] = *(const uint32_t*)(Ql + (size_t)r0 * HDIM + c0);
        ql[j][1] = *(const uint32_t*)(Ql + (size_t)(r0 + 8) * HDIM + c0);
        ql[j][2] = *(const uint32_t*)(Ql + (size_t)r0 * HDIM + c0 + 8);
        ql[j][3] = *(const uint32_t*)(Ql + (size_t)(r0 + 8) * HDIM + c0 + 8);
    }

    float o[8][4] = {};
    float mx0 = -1e30f, mx1 = -1e30f, l0 = 0.f, l1 = 0.f;

    auto stage_load = [&](int buf, int c) {
        const int s0 = c * 64;
        const uint32_t so = sb + buf * STAGE;
#pragma unroll
        for (int i = tid; i < 512; i += 256) {
            int r = i >> 3, cc = i & 7;
            uint32_t off = r * ROWB + cc * 16;
            cp16(so + 0 * TILE + off, Kh + (size_t)(s0 + r) * HDIM + cc * 8);
            cp16(so + 1 * TILE + off, Kl + (size_t)(s0 + r) * HDIM + cc * 8);
            cp16(so + 2 * TILE + off, Vh + (size_t)r * SEQ + s0 + cc * 8);
            cp16(so + 3 * TILE + off, Vl + (size_t)r * SEQ + s0 + cc * 8);
        }
        asm volatile("cp.async.commit_group;");
    };

    stage_load(0, 0);
    for (int c = 0; c < NCH; c++) {
        const int buf = c & 1;
        if (c + 1 < NCH) {
            stage_load(buf ^ 1, c + 1);
            asm volatile("cp.async.wait_group 1;");
        } else {
            asm volatile("cp.async.wait_group 0;");
        }
        __syncthreads();
        const char* sK = smem + buf * STAGE;
        const char* sV = sK + 2 * TILE;

        // ---- S = Q @ K^T (3-term split) ----
        float sa[8][4] = {};
#pragma unroll
        for (int j = 0; j < 4; j++) {
            const int kb = j * 32 + t * 4;
#pragma unroll
            for (int nt = 0; nt < 8; nt++) {
                const char* p = sK + (nt * 8 + g) * ROWB + kb;
                uint32_t bhf[2] = {*(const uint32_t*)p, *(const uint32_t*)(p + 16)};
                uint32_t blf[2] = {*(const uint32_t*)(p + TILE), *(const uint32_t*)(p + TILE + 16)};
                mma_bf16(sa[nt], qh[j], bhf);
                mma_bf16(sa[nt], ql[j], bhf);
                mma_bf16(sa[nt], qh[j], blf);
            }
        }

        // ---- online softmax ----
        float cm0 = -1e30f, cm1 = -1e30f;
#pragma unroll
        for (int nt = 0; nt < 8; nt++) {
            cm0 = fmaxf(cm0, fmaxf(sa[nt][0], sa[nt][1]));
            cm1 = fmaxf(cm1, fmaxf(sa[nt][2], sa[nt][3]));
        }
#pragma unroll
        for (int off = 1; off <= 2; off <<= 1) {
            cm0 = fmaxf(cm0, __shfl_xor_sync(0xffffffffu, cm0, off));
            cm1 = fmaxf(cm1, __shfl_xor_sync(0xffffffffu, cm1, off));
        }
        float m0n = fmaxf(mx0, cm0), m1n = fmaxf(mx1, cm1);
        float a0 = __expf(mx0 - m0n), a1 = __expf(mx1 - m1n);
        mx0 = m0n; mx1 = m1n;

        float ps0 = 0.f, ps1 = 0.f;
#pragma unroll
        for (int nt = 0; nt < 8; nt++) {
            sa[nt][0] = __expf(sa[nt][0] - m0n);
            sa[nt][1] = __expf(sa[nt][1] - m0n);
            sa[nt][2] = __expf(sa[nt][2] - m1n);
            sa[nt][3] = __expf(sa[nt][3] - m1n);
            ps0 += sa[nt][0] + sa[nt][1];
            ps1 += sa[nt][2] + sa[nt][3];
        }
#pragma unroll
        for (int off = 1; off <= 2; off <<= 1) {
            ps0 += __shfl_xor_sync(0xffffffffu, ps0, off);
            ps1 += __shfl_xor_sync(0xffffffffu, ps1, off);
        }
        l0 = l0 * a0 + ps0;
        l1 = l1 * a1 + ps1;
#pragma unroll
        for (int nt = 0; nt < 8; nt++) {
            o[nt][0] *= a0; o[nt][1] *= a0; o[nt][2] *= a1; o[nt][3] *= a1;
        }

        // ---- P fragments (hi/lo split in registers) ----
        uint32_t ph[4][4], pl[4][4];
#pragma unroll
        for (int j = 0; j < 4; j++) {
            split2(sa[2 * j][0],     sa[2 * j][1],     ph[j][0], pl[j][0]);
            split2(sa[2 * j][2],     sa[2 * j][3],     ph[j][1], pl[j][1]);
            split2(sa[2 * j + 1][0], sa[2 * j + 1][1], ph[j][2], pl[j][2]);
            split2(sa[2 * j + 1][2], sa[2 * j + 1][3], ph[j][3], pl[j][3]);
        }

        // ---- O += P @ V (3-term split) ----
#pragma unroll
        for (int j = 0; j < 4; j++) {
            const int kb = j * 32 + t * 4;
#pragma unroll
            for (int nt = 0; nt < 8; nt++) {
                const char* p = sV + (nt * 8 + g) * ROWB + kb;
                uint32_t bhf[2] = {*(const uint32_t*)p, *(const uint32_t*)(p + 16)};
                uint32_t blf[2] = {*(const uint32_t*)(p + TILE), *(const uint32_t*)(p + TILE + 16)};
                mma_bf16(o[nt], ph[j], bhf);
                mma_bf16(o[nt], pl[j], bhf);
                mma_bf16(o[nt], ph[j], blf);
            }
        }
        __syncthreads();
    }

    // ---- epilogue: merged-head hi/lo output ----
    const float i0 = 1.0f / l0, i1 = 1.0f / l1;
    const int b = bh >> 4, h = bh & (NH - 1);
#pragma unroll
    for (int nt = 0; nt < 8; nt++) {
        int col = h * HDIM + nt * 8 + 2 * t;
        size_t adr0 = ((size_t)b * SEQ + r0) * DIM + col;
        size_t adr1 = ((size_t)b * SEQ + r0 + 8) * DIM + col;
        uint32_t hh, ll;
        split2(o[nt][0] * i0, o[nt][1] * i0, hh, ll);
        *(uint32_t*)(g_Ah + adr0) = hh;
        *(uint32_t*)(g_Al + adr0) = ll;
        split2(o[nt][2] * i1, o[nt][3] * i1, hh, ll);
        *(uint32_t*)(g_Ah + adr1) = hh;
        *(uint32_t*)(g_Al + adr1) = ll;
    }
}

// ---------------- host ----------------
static void* sym(const void* s) { void* p; cudaGetSymbolAddress(&p, s); return p; }

extern "C" void kernel_launch(void* const* d_in, const int* in_sizes, int n_in,
                              void* d_out, int out_size)
{
    const float* x  = (const float*)d_in[0];
    const float* Wq = (const float*)d_in[1];
    const float* bq = (const float*)d_in[2];
    const float* Wk = (const float*)d_in[3];
    const float* bk = (const float*)d_in[4];
    const float* Wv = (const float*)d_in[5];
    const float* bv = (const float*)d_in[6];
    const float* Wo = (const float*)d_in[7];
    const float* bo = (const float*)d_in[8];
    float* out = (float*)d_out;

    constexpr int SMEMG = 2 * 4 * 128 * 80;   // 81920
    constexpr int SMEMF = 2 * 4 * 64 * 144;   // 73728
    cudaFuncSetAttribute(gemm_kernel,  cudaFuncAttributeMaxDynamicSharedMemorySize, SMEMG);
    cudaFuncSetAttribute(flash_kernel, cudaFuncAttributeMaxDynamicSharedMemorySize, SMEMF);

    __nv_bfloat16 *xh = (__nv_bfloat16*)sym(g_xh), *xl = (__nv_bfloat16*)sym(g_xl);
    __nv_bfloat16 *wqh = (__nv_bfloat16*)sym(g_Wqh), *wql = (__nv_bfloat16*)sym(g_Wql);
    __nv_bfloat16 *wkh = (__nv_bfloat16*)sym(g_Wkh), *wkl = (__nv_bfloat16*)sym(g_Wkl);
    __nv_bfloat16 *wvh = (__nv_bfloat16*)sym(g_Wvh), *wvl = (__nv_bfloat16*)sym(g_Wvl);
    __nv_bfloat16 *woh = (__nv_bfloat16*)sym(g_Woh), *wol = (__nv_bfloat16*)sym(g_Wol);
    __nv_bfloat16 *qh = (__nv_bfloat16*)sym(g_Qh), *ql = (__nv_bfloat16*)sym(g_Ql);
    __nv_bfloat16 *kh = (__nv_bfloat16*)sym(g_Kh), *kl = (__nv_bfloat16*)sym(g_Kl);
    __nv_bfloat16 *vth = (__nv_bfloat16*)sym(g_Vth), *vtl = (__nv_bfloat16*)sym(g_Vtl);
    __nv_bfloat16 *ah = (__nv_bfloat16*)sym(g_Ah), *al = (__nv_bfloat16*)sym(g_Al);

    split_kernel<<<(MROWS * DIM + 255) / 256, 256>>>(x, xh, xl, MROWS * DIM);
    dim3 wg(DIM / 32, DIM / 32);
    wsplit_kernel<<<wg, 256>>>(Wq, wqh, wql);
    wsplit_kernel<<<wg, 256>>>(Wk, wkh, wkl);
    wsplit_kernel<<<wg, 256>>>(Wv, wvh, wvl);
    wsplit_kernel<<<wg, 256>>>(Wo, woh, wol);

    dim3 blk(256);
    dim3 gproj(DIM / 128, MROWS / 128);

    gemm_kernel<<<gproj, blk, SMEMG>>>(xh, xl, wqh, wql, bq, 0.125f, 0, qh, ql, nullptr);
    gemm_kernel<<<gproj, blk, SMEMG>>>(xh, xl, wkh, wkl, bk, 1.0f,   0, kh, kl, nullptr);
    gemm_kernel<<<gproj, blk, SMEMG>>>(xh, xl, wvh, wvl, bv, 1.0f,   1, vth, vtl, nullptr);

    flash_kernel<<<dim3(SEQ / 128, BH), blk, SMEMF>>>();

    gemm_kernel<<<gproj, blk, SMEMG>>>(ah, al, woh, wol, bo, 1.0f, 2, nullptr, nullptr, out);
}